// round 1
// baseline (speedup 1.0000x reference)
#include <cuda_runtime.h>
#include <math.h>
#include <stdint.h>

// ---------------- problem constants ----------------
#define BGR   128          // graphs
#define NPER0 512          // nodes per graph, layer 0
#define EPG   8192         // edges per graph
#define EE    (BGR*EPG)    // 1048576 total edges
#define N0    (BGR*NPER0)  // 65536
#define K1    410
#define K2    328
#define N1    (BGR*K1)     // 52480
#define N2    (BGR*K2)     // 41984
#define HF    128          // feature dim (DIN == H == 128)
#define DOUT  10
#define BN_EPS 1e-5f

// ---------------- static device scratch (no runtime alloc allowed) ----------------
__device__ float g_bufA[(size_t)N0*HF];   // GCN output h_out
__device__ float g_bufB[(size_t)N0*HF];   // X@W result; later reused for hp2
__device__ float g_bufC[(size_t)N1*HF];   // hp1 (post pool+BN layer0)
__device__ float g_dinv[N0];
__device__ float g_hs[N0];
__device__ float g_sc[N0];
__device__ int   g_remap[N0];
__device__ int   g_rowbase[N0];
__device__ int   g_rowcnt[N0];
__device__ int   g_csrsrc[EE];
__device__ int   g_src1[EE];
__device__ int   g_dst1[EE];
__device__ float g_pool0[BGR*HF];
__device__ float g_pool1[BGR*HF];
__device__ float g_pool2[BGR*HF];

// ---------------- CSR build per graph + degree/dinv ----------------
// One CTA (512 threads) per graph. src<0 marks masked edge (layer>=1).
__global__ void k_csr(const int* __restrict__ src, const int* __restrict__ dst,
                      int nper, int* __restrict__ row_base, int* __restrict__ row_cnt,
                      int* __restrict__ csr_src, float* __restrict__ dinv) {
    __shared__ int cnt[512];
    __shared__ int off[512];
    __shared__ int cur[512];
    int g = blockIdx.x, i = threadIdx.x;
    cnt[i] = 0; cur[i] = 0;
    __syncthreads();
    int ebase = g * EPG;
    #pragma unroll
    for (int t = i; t < EPG; t += 512) {
        int s = src[ebase + t];
        if (s >= 0) atomicAdd(&cnt[dst[ebase + t] - g * nper], 1);
    }
    __syncthreads();
    int c = cnt[i];
    off[i] = c;
    __syncthreads();
    // Hillis-Steele inclusive scan over 512
    for (int d = 1; d < 512; d <<= 1) {
        int t = (i >= d) ? off[i - d] : 0;
        __syncthreads();
        off[i] += t;
        __syncthreads();
    }
    int excl = off[i] - c;
    if (i < nper) {
        row_cnt[g * nper + i]  = c;
        row_base[g * nper + i] = ebase + excl;
        dinv[g * nper + i]     = rsqrtf(1.0f + (float)c);  // +1 self loop
    }
    __syncthreads();
    off[i] = excl;
    __syncthreads();
    for (int t = i; t < EPG; t += 512) {
        int s = src[ebase + t];
        if (s >= 0) {
            int d = dst[ebase + t] - g * nper;
            int p = atomicAdd(&cur[d], 1);
            csr_src[ebase + off[d] + p] = s;
        }
    }
}

// ---------------- GEMM: Y[nrows,128] = X[nrows,128] @ W[128,128] ----------------
// Block: 256 threads, tile 32 rows x 128 cols, per-thread 4x4 micro-tile.
__global__ void k_gemm128(const float* __restrict__ X, const float* __restrict__ W,
                          float* __restrict__ Y, int nrows) {
    __shared__ float Xs[32][HF];
    int row0 = blockIdx.x * 32;
    int tid = threadIdx.x;
    for (int i = tid; i < 32 * 32; i += 256) {   // float4 granularity
        int r = i >> 5, c4 = i & 31;
        float4 v = make_float4(0.f, 0.f, 0.f, 0.f);
        if (row0 + r < nrows)
            v = *(const float4*)(X + (size_t)(row0 + r) * HF + c4 * 4);
        *(float4*)(&Xs[r][c4 * 4]) = v;
    }
    __syncthreads();
    int wid = tid >> 5, lane = tid & 31;
    int r0 = wid * 4, c0 = lane * 4;
    float acc[4][4] = {};
    #pragma unroll 8
    for (int k = 0; k < HF; k++) {
        float4 b = *(const float4*)(W + (size_t)k * HF + c0);
        float a0 = Xs[r0][k], a1 = Xs[r0 + 1][k], a2 = Xs[r0 + 2][k], a3 = Xs[r0 + 3][k];
        acc[0][0] += a0 * b.x; acc[0][1] += a0 * b.y; acc[0][2] += a0 * b.z; acc[0][3] += a0 * b.w;
        acc[1][0] += a1 * b.x; acc[1][1] += a1 * b.y; acc[1][2] += a1 * b.z; acc[1][3] += a1 * b.w;
        acc[2][0] += a2 * b.x; acc[2][1] += a2 * b.y; acc[2][2] += a2 * b.z; acc[2][3] += a2 * b.w;
        acc[3][0] += a3 * b.x; acc[3][1] += a3 * b.y; acc[3][2] += a3 * b.z; acc[3][3] += a3 * b.w;
    }
    #pragma unroll
    for (int i = 0; i < 4; i++) {
        int r = row0 + r0 + i;
        if (r < nrows) {
            float4 o = make_float4(acc[i][0], acc[i][1], acc[i][2], acc[i][3]);
            *(float4*)(Y + (size_t)r * HF + c0) = o;
        }
    }
}

// ---------------- GCN aggregation (warp per dst node, no atomics) ----------------
// out[v] = sum_{e in csr(v)} dinv[src]*dinv[v]*H[src] + H[v]*dinv[v]^2 + bias
__global__ void k_agg(const float* __restrict__ H,
                      const int* __restrict__ csr_src,
                      const int* __restrict__ row_base, const int* __restrict__ row_cnt,
                      const float* __restrict__ dinv, const float* __restrict__ bias,
                      float* __restrict__ out, int n) {
    int w = (blockIdx.x * blockDim.x + threadIdx.x) >> 5;
    int lane = threadIdx.x & 31;
    if (w >= n) return;
    float di = dinv[w];
    int base = row_base[w], cnt = row_cnt[w];
    float ax = 0.f, ay = 0.f, az = 0.f, aw = 0.f;
    int c0 = lane * 4;
    for (int e = 0; e < cnt; e++) {
        int s = __ldg(&csr_src[base + e]);
        float c = __ldg(&dinv[s]);
        float4 hv = *(const float4*)(H + (size_t)s * HF + c0);
        ax += c * hv.x; ay += c * hv.y; az += c * hv.z; aw += c * hv.w;
    }
    float sd = di * di;
    float4 self = *(const float4*)(H + (size_t)w * HF + c0);
    float4 b4 = *(const float4*)(bias + c0);
    float4 o;
    o.x = ax * di + self.x * sd + b4.x;
    o.y = ay * di + self.y * sd + b4.y;
    o.z = az * di + self.z * sd + b4.z;
    o.w = aw * di + self.w * sd + b4.w;
    *(float4*)(out + (size_t)w * HF + c0) = o;
}

// ---------------- score matvec: hs[v] = dot(Hout[v], sW) (warp per node) ----------------
__global__ void k_hs(const float* __restrict__ Hout, const float* __restrict__ sW,
                     float* __restrict__ hs, int n) {
    int w = (blockIdx.x * blockDim.x + threadIdx.x) >> 5;
    int lane = threadIdx.x & 31;
    if (w >= n) return;
    float4 h = *(const float4*)(Hout + (size_t)w * HF + lane * 4);
    float4 wv = *(const float4*)(sW + lane * 4);
    float d = h.x * wv.x + h.y * wv.y + h.z * wv.z + h.w * wv.w;
    #pragma unroll
    for (int off = 16; off > 0; off >>= 1) d += __shfl_down_sync(0xFFFFFFFFu, d, off);
    if (lane == 0) hs[w] = d;
}

// ---------------- scalar score aggregation ----------------
__global__ void k_sagg(const float* __restrict__ hs,
                       const int* __restrict__ csr_src,
                       const int* __restrict__ row_base, const int* __restrict__ row_cnt,
                       const float* __restrict__ dinv, const float* __restrict__ sb,
                       float* __restrict__ s, int n) {
    int v = blockIdx.x * blockDim.x + threadIdx.x;
    if (v >= n) return;
    float di = dinv[v];
    int base = row_base[v], cnt = row_cnt[v];
    float acc = 0.f;
    for (int e = 0; e < cnt; e++) {
        int u = __ldg(&csr_src[base + e]);
        acc += __ldg(&hs[u]) * __ldg(&dinv[u]);
    }
    s[v] = acc * di + hs[v] * di * di + sb[0];
}

// ---------------- per-graph top-k selection (exact rank, ties -> lower index) ----------------
__global__ void k_pool_select(const float* __restrict__ s, int nper, int k,
                              int* __restrict__ remap) {
    __shared__ float sc[512];
    __shared__ int keep[512];
    int g = blockIdx.x, i = threadIdx.x;
    sc[i] = (i < nper) ? s[g * nper + i] : -1e30f;
    __syncthreads();
    int kept = 0;
    if (i < nper) {
        float si = sc[i];
        int rank = 0;
        for (int j = 0; j < nper; j++) {
            float sj = sc[j];
            rank += (sj > si) || (sj == si && j < i);
        }
        kept = (rank < k) ? 1 : 0;
    }
    keep[i] = kept;
    __syncthreads();
    for (int d = 1; d < 512; d <<= 1) {
        int t = (i >= d) ? keep[i - d] : 0;
        __syncthreads();
        keep[i] += t;
        __syncthreads();
    }
    if (i < nper)
        remap[g * nper + i] = kept ? (g * k + keep[i] - 1) : -1;
}

// ---------------- pool copy fused with tanh-gate + BatchNorm + ReLU ----------------
__global__ void k_pool_copy(const float* __restrict__ Hout, const float* __restrict__ s,
                            const int* __restrict__ remap,
                            const float* __restrict__ bg, const float* __restrict__ bb,
                            const float* __restrict__ bm, const float* __restrict__ bv,
                            float* __restrict__ hp, int n_old) {
    int v = (blockIdx.x * blockDim.x + threadIdx.x) >> 5;
    int lane = threadIdx.x & 31;
    if (v >= n_old) return;
    int r = remap[v];
    if (r < 0) return;
    float t = tanhf(s[v]);
    int c0 = lane * 4;
    float4 h  = *(const float4*)(Hout + (size_t)v * HF + c0);
    float4 g4 = *(const float4*)(bg + c0);
    float4 b4 = *(const float4*)(bb + c0);
    float4 m4 = *(const float4*)(bm + c0);
    float4 v4 = *(const float4*)(bv + c0);
    float4 o;
    o.x = fmaxf(g4.x * (h.x * t - m4.x) * rsqrtf(v4.x + BN_EPS) + b4.x, 0.f);
    o.y = fmaxf(g4.y * (h.y * t - m4.y) * rsqrtf(v4.y + BN_EPS) + b4.y, 0.f);
    o.z = fmaxf(g4.z * (h.z * t - m4.z) * rsqrtf(v4.z + BN_EPS) + b4.z, 0.f);
    o.w = fmaxf(g4.w * (h.w * t - m4.w) * rsqrtf(v4.w + BN_EPS) + b4.w, 0.f);
    *(float4*)(hp + (size_t)r * HF + c0) = o;
}

// ---------------- edge remap / mask ----------------
__global__ void k_remap_edges(const int* __restrict__ src_in, const int* __restrict__ dst_in,
                              const int* __restrict__ remap,
                              int* __restrict__ src_out, int* __restrict__ dst_out) {
    int e = blockIdx.x * blockDim.x + threadIdx.x;
    if (e >= EE) return;
    int si = src_in[e];
    int s2 = -1, d2 = -1;
    if (si >= 0) {
        s2 = remap[si];
        d2 = remap[dst_in[e]];
        if (s2 < 0 || d2 < 0) { s2 = -1; d2 = -1; }
    }
    src_out[e] = s2;
    dst_out[e] = d2;
}

// ---------------- per-graph feature sum ----------------
__global__ void k_pooled(const float* __restrict__ X, int nper, float* __restrict__ P) {
    int g = blockIdx.x, f = threadIdx.x;   // 128 threads
    const float* base = X + (size_t)g * nper * HF + f;
    float acc = 0.f;
    for (int r = 0; r < nper; r++) acc += base[(size_t)r * HF];
    P[g * HF + f] = acc;
}

// ---------------- readout: out[b][o] = sum_i pooled_i @ lin_i^T + sum_i b_i ----------------
__global__ void k_final(const float* __restrict__ P0, const float* __restrict__ P1,
                        const float* __restrict__ P2,
                        const float* __restrict__ W0, const float* __restrict__ b0,
                        const float* __restrict__ W1, const float* __restrict__ b1,
                        const float* __restrict__ W2, const float* __restrict__ b2,
                        float* __restrict__ out) {
    int idx = blockIdx.x * blockDim.x + threadIdx.x;
    if (idx >= BGR * DOUT) return;
    int b = idx / DOUT, o = idx % DOUT;
    float acc = b0[o] + b1[o] + b2[o];
    const float* p0 = P0 + b * HF;
    const float* p1 = P1 + b * HF;
    const float* p2 = P2 + b * HF;
    const float* w0 = W0 + o * HF;
    const float* w1 = W1 + o * HF;
    const float* w2 = W2 + o * HF;
    #pragma unroll 4
    for (int f = 0; f < HF; f++)
        acc += p0[f] * w0[f] + p1[f] * w1[f] + p2[f] * w2[f];
    out[idx] = acc;
}

// ---------------- host launch ----------------
extern "C" void kernel_launch(void* const* d_in, const int* in_sizes, int n_in,
                              void* d_out, int out_size) {
    const float* x        = (const float*)d_in[0];
    const int*   ei       = (const int*)  d_in[1];
    const float* conv1_W  = (const float*)d_in[2];
    const float* conv1_b  = (const float*)d_in[3];
    const float* conv2_W  = (const float*)d_in[4];
    const float* conv2_b  = (const float*)d_in[5];
    const float* score1_W = (const float*)d_in[6];
    const float* score1_b = (const float*)d_in[7];
    const float* score2_W = (const float*)d_in[8];
    const float* score2_b = (const float*)d_in[9];
    const float* bn1_g    = (const float*)d_in[10];
    const float* bn1_b    = (const float*)d_in[11];
    const float* bn1_m    = (const float*)d_in[12];
    const float* bn1_v    = (const float*)d_in[13];
    const float* bn2_g    = (const float*)d_in[14];
    const float* bn2_b    = (const float*)d_in[15];
    const float* bn2_m    = (const float*)d_in[16];
    const float* bn2_v    = (const float*)d_in[17];
    const float* lin0_W   = (const float*)d_in[18];
    const float* lin0_b   = (const float*)d_in[19];
    const float* lin1_W   = (const float*)d_in[20];
    const float* lin1_b   = (const float*)d_in[21];
    const float* lin2_W   = (const float*)d_in[22];
    const float* lin2_b   = (const float*)d_in[23];
    float* out = (float*)d_out;

    const int* src0 = ei;          // edge_index row 0
    const int* dst0 = ei + EE;     // edge_index row 1

    float *bufA, *bufB, *bufC, *dinv, *hs, *sc, *p0, *p1, *p2;
    int *remap, *rowbase, *rowcnt, *csrsrc, *src1, *dst1;
    cudaGetSymbolAddress((void**)&bufA,   g_bufA);
    cudaGetSymbolAddress((void**)&bufB,   g_bufB);
    cudaGetSymbolAddress((void**)&bufC,   g_bufC);
    cudaGetSymbolAddress((void**)&dinv,   g_dinv);
    cudaGetSymbolAddress((void**)&hs,     g_hs);
    cudaGetSymbolAddress((void**)&sc,     g_sc);
    cudaGetSymbolAddress((void**)&remap,  g_remap);
    cudaGetSymbolAddress((void**)&rowbase,g_rowbase);
    cudaGetSymbolAddress((void**)&rowcnt, g_rowcnt);
    cudaGetSymbolAddress((void**)&csrsrc, g_csrsrc);
    cudaGetSymbolAddress((void**)&src1,   g_src1);
    cudaGetSymbolAddress((void**)&dst1,   g_dst1);
    cudaGetSymbolAddress((void**)&p0,     g_pool0);
    cudaGetSymbolAddress((void**)&p1,     g_pool1);
    cudaGetSymbolAddress((void**)&p2,     g_pool2);

    // ---------- layer 0 ----------
    k_csr<<<BGR, 512>>>(src0, dst0, NPER0, rowbase, rowcnt, csrsrc, dinv);
    k_gemm128<<<(N0 + 31) / 32, 256>>>(x, conv1_W, bufB, N0);
    k_agg<<<(N0 + 7) / 8, 256>>>(bufB, csrsrc, rowbase, rowcnt, dinv, conv1_b, bufA, N0);
    k_hs<<<(N0 + 7) / 8, 256>>>(bufA, score1_W, hs, N0);
    k_sagg<<<(N0 + 255) / 256, 256>>>(hs, csrsrc, rowbase, rowcnt, dinv, score1_b, sc, N0);
    k_pool_select<<<BGR, 512>>>(sc, NPER0, K1, remap);
    k_pool_copy<<<(N0 + 7) / 8, 256>>>(bufA, sc, remap, bn1_g, bn1_b, bn1_m, bn1_v, bufC, N0);
    k_remap_edges<<<(EE + 255) / 256, 256>>>(src0, dst0, remap, src1, dst1);

    // ---------- layer 1 ----------
    k_csr<<<BGR, 512>>>(src1, dst1, K1, rowbase, rowcnt, csrsrc, dinv);
    k_gemm128<<<(N1 + 31) / 32, 256>>>(bufC, conv2_W, bufB, N1);
    k_agg<<<(N1 + 7) / 8, 256>>>(bufB, csrsrc, rowbase, rowcnt, dinv, conv2_b, bufA, N1);
    k_hs<<<(N1 + 7) / 8, 256>>>(bufA, score2_W, hs, N1);
    k_sagg<<<(N1 + 255) / 256, 256>>>(hs, csrsrc, rowbase, rowcnt, dinv, score2_b, sc, N1);
    k_pool_select<<<BGR, 512>>>(sc, K1, K2, remap);
    // hp2 goes into bufB (X@W no longer needed)
    k_pool_copy<<<(N1 + 7) / 8, 256>>>(bufA, sc, remap, bn2_g, bn2_b, bn2_m, bn2_v, bufB, N1);

    // ---------- readout ----------
    k_pooled<<<BGR, HF>>>(x,    NPER0, p0);
    k_pooled<<<BGR, HF>>>(bufC, K1,    p1);
    k_pooled<<<BGR, HF>>>(bufB, K2,    p2);
    k_final<<<(BGR * DOUT + 255) / 256, 256>>>(p0, p1, p2,
                                               lin0_W, lin0_b, lin1_W, lin1_b, lin2_W, lin2_b,
                                               out);
}

// round 2
// speedup vs baseline: 1.0606x; 1.0606x over previous
#include <cuda_runtime.h>
#include <math.h>
#include <stdint.h>

// ---------------- problem constants ----------------
#define BGR   128          // graphs
#define NPER0 512          // nodes per graph, layer 0
#define EPG   8192         // edges per graph
#define EE    (BGR*EPG)    // 1048576 total edges
#define N0    (BGR*NPER0)  // 65536
#define K1    410
#define K2    328
#define N1    (BGR*K1)     // 52480
#define N2    (BGR*K2)     // 41984
#define HF    128          // feature dim (DIN == H == 128)
#define DOUT  10
#define BN_EPS 1e-5f

typedef unsigned long long u64;

// ---------------- static device scratch ----------------
__device__ float g_bufA[(size_t)N0*HF];   // GCN output h
__device__ float g_bufB[(size_t)N0*HF];   // X@W ; later hp2
__device__ float g_bufC[(size_t)N1*HF];   // hp1
__device__ float g_dinv[N0];
__device__ float g_hs[N0];
__device__ float g_sc[N0];
__device__ int   g_remap[N0];
__device__ int   g_rowbase[N0];
__device__ int   g_rowcnt[N0];
__device__ int   g_csrsrc[EE];
__device__ u64   g_Wp1[64*HF];            // packed (W[2k][c], W[2k+1][c])
__device__ u64   g_Wp2[64*HF];
__device__ float g_pool0[BGR*HF];
__device__ float g_pool1[BGR*HF];
__device__ float g_pool2[BGR*HF];

// ---------------- packed fp32x2 fma ----------------
__device__ __forceinline__ u64 ffma2(u64 a, u64 b, u64 c) {
    u64 d;
    asm("fma.rn.f32x2 %0, %1, %2, %3;" : "=l"(d) : "l"(a), "l"(b), "l"(c));
    return d;
}

// ---------------- pack W pairs: Wp[kp*128+c] = (W[2kp][c], W[2kp+1][c]) ----------------
__global__ void k_packW(const float* __restrict__ W, u64* __restrict__ Wp) {
    int i = blockIdx.x * blockDim.x + threadIdx.x;
    if (i >= 64 * HF) return;
    int kp = i >> 7, c = i & 127;
    u64 lo = __float_as_uint(W[(2 * kp) * HF + c]);
    u64 hi = __float_as_uint(W[(2 * kp + 1) * HF + c]);
    Wp[i] = lo | (hi << 32);
}

// ---------------- CSR build per graph (+ optional remap fusion) ----------------
__global__ void k_csr(const int* __restrict__ src, const int* __restrict__ dst,
                      const int* __restrict__ remap, int nper,
                      int* __restrict__ row_base, int* __restrict__ row_cnt,
                      int* __restrict__ csr_src, float* __restrict__ dinv) {
    __shared__ int cnt[512];
    __shared__ int off[512];
    __shared__ int cur[512];
    int g = blockIdx.x, i = threadIdx.x;
    cnt[i] = 0; cur[i] = 0;
    __syncthreads();
    int ebase = g * EPG;
    for (int t = i; t < EPG; t += 512) {
        int s = src[ebase + t];
        int d = dst[ebase + t];
        if (remap) {
            s = remap[s];
            d = (s >= 0) ? remap[d] : -1;
            if (d < 0) continue;
        }
        atomicAdd(&cnt[d - g * nper], 1);
    }
    __syncthreads();
    int c = cnt[i];
    off[i] = c;
    __syncthreads();
    for (int d = 1; d < 512; d <<= 1) {          // Hillis-Steele inclusive scan
        int t = (i >= d) ? off[i - d] : 0;
        __syncthreads();
        off[i] += t;
        __syncthreads();
    }
    int excl = off[i] - c;
    if (i < nper) {
        row_cnt[g * nper + i]  = c;
        row_base[g * nper + i] = ebase + excl;
        dinv[g * nper + i]     = rsqrtf(1.0f + (float)c);  // +1 self loop
    }
    __syncthreads();
    off[i] = excl;
    __syncthreads();
    for (int t = i; t < EPG; t += 512) {
        int s = src[ebase + t];
        int d = dst[ebase + t];
        if (remap) {
            s = remap[s];
            d = (s >= 0) ? remap[d] : -1;
            if (d < 0) continue;
        }
        int dl = d - g * nper;
        int p = atomicAdd(&cur[dl], 1);
        csr_src[ebase + off[dl] + p] = s;
    }
}

// ---------------- GEMM: Y[nrows,128] = X[nrows,128] @ W, packed f32x2 (2 K/inst) ----
// 256 threads, 64-row tile; thread: 8 rows x 4 cols; acc holds 2 K-partials packed.
__global__ void k_gemm2(const float* __restrict__ X, const u64* __restrict__ Wp,
                        float* __restrict__ Y, int nrows) {
    __shared__ float Xs[64][HF];
    int row0 = blockIdx.x * 64;
    int tid = threadIdx.x;
    #pragma unroll
    for (int j = 0; j < 8; j++) {
        int idx = j * 256 + tid;
        int r = idx >> 5, c4 = idx & 31;
        float4 v = make_float4(0.f, 0.f, 0.f, 0.f);
        if (row0 + r < nrows)
            v = *(const float4*)(X + (size_t)(row0 + r) * HF + c4 * 4);
        *(float4*)(&Xs[r][c4 * 4]) = v;
    }
    __syncthreads();
    int wid = tid >> 5, lane = tid & 31;
    int r0 = wid * 8, c0 = lane * 4;
    u64 acc[8][4] = {};
    const u64* wp = Wp + c0;
    #pragma unroll 8
    for (int kp = 0; kp < 64; kp++) {
        ulonglong2 b01 = *(const ulonglong2*)(wp + (size_t)kp * HF);
        ulonglong2 b23 = *(const ulonglong2*)(wp + (size_t)kp * HF + 2);
        #pragma unroll
        for (int i = 0; i < 8; i++) {
            u64 a = *(const u64*)(&Xs[r0 + i][kp * 2]);   // (X[r][2kp], X[r][2kp+1])
            acc[i][0] = ffma2(a, b01.x, acc[i][0]);
            acc[i][1] = ffma2(a, b01.y, acc[i][1]);
            acc[i][2] = ffma2(a, b23.x, acc[i][2]);
            acc[i][3] = ffma2(a, b23.y, acc[i][3]);
        }
    }
    #pragma unroll
    for (int i = 0; i < 8; i++) {
        int r = row0 + r0 + i;
        if (r < nrows) {
            float4 o;
            float2 p0 = *(float2*)&acc[i][0];
            float2 p1 = *(float2*)&acc[i][1];
            float2 p2 = *(float2*)&acc[i][2];
            float2 p3 = *(float2*)&acc[i][3];
            o.x = p0.x + p0.y; o.y = p1.x + p1.y; o.z = p2.x + p2.y; o.w = p3.x + p3.y;
            *(float4*)(Y + (size_t)r * HF + c0) = o;
        }
    }
}

// ---------------- GCN aggregation fused with score matvec (warp per dst node) ----
__global__ void k_agg_hs(const float* __restrict__ H,
                         const int* __restrict__ csr_src,
                         const int* __restrict__ row_base, const int* __restrict__ row_cnt,
                         const float* __restrict__ dinv, const float* __restrict__ bias,
                         const float* __restrict__ sW,
                         float* __restrict__ out, float* __restrict__ hs, int n) {
    int w = (blockIdx.x * blockDim.x + threadIdx.x) >> 5;
    int lane = threadIdx.x & 31;
    if (w >= n) return;
    float di = dinv[w];
    int base = row_base[w], cnt = row_cnt[w];
    float ax = 0.f, ay = 0.f, az = 0.f, aw = 0.f;
    int c0 = lane * 4;
    for (int e = 0; e < cnt; e++) {
        int s = __ldg(&csr_src[base + e]);
        float c = __ldg(&dinv[s]);
        float4 hv = *(const float4*)(H + (size_t)s * HF + c0);
        ax += c * hv.x; ay += c * hv.y; az += c * hv.z; aw += c * hv.w;
    }
    float sd = di * di;
    float4 self = *(const float4*)(H + (size_t)w * HF + c0);
    float4 b4 = *(const float4*)(bias + c0);
    float4 o;
    o.x = ax * di + self.x * sd + b4.x;
    o.y = ay * di + self.y * sd + b4.y;
    o.z = az * di + self.z * sd + b4.z;
    o.w = aw * di + self.w * sd + b4.w;
    *(float4*)(out + (size_t)w * HF + c0) = o;
    // fused score matvec
    float4 wv = *(const float4*)(sW + c0);
    float d = o.x * wv.x + o.y * wv.y + o.z * wv.z + o.w * wv.w;
    #pragma unroll
    for (int off = 16; off > 0; off >>= 1) d += __shfl_down_sync(0xFFFFFFFFu, d, off);
    if (lane == 0) hs[w] = d;
}

// ---------------- scalar score aggregation ----------------
__global__ void k_sagg(const float* __restrict__ hs,
                       const int* __restrict__ csr_src,
                       const int* __restrict__ row_base, const int* __restrict__ row_cnt,
                       const float* __restrict__ dinv, const float* __restrict__ sb,
                       float* __restrict__ s, int n) {
    int v = blockIdx.x * blockDim.x + threadIdx.x;
    if (v >= n) return;
    float di = dinv[v];
    int base = row_base[v], cnt = row_cnt[v];
    float acc = 0.f;
    for (int e = 0; e < cnt; e++) {
        int u = __ldg(&csr_src[base + e]);
        acc += __ldg(&hs[u]) * __ldg(&dinv[u]);
    }
    s[v] = acc * di + hs[v] * di * di + sb[0];
}

// ---------------- per-graph top-k selection (exact rank, ties -> lower index) ----
__global__ void k_pool_select(const float* __restrict__ s, int nper, int k,
                              int* __restrict__ remap) {
    __shared__ float sc[512];
    __shared__ int keep[512];
    int g = blockIdx.x, i = threadIdx.x;
    sc[i] = (i < nper) ? s[g * nper + i] : -1e30f;
    __syncthreads();
    int kept = 0;
    if (i < nper) {
        float si = sc[i];
        int rank = 0;
        for (int j = 0; j < nper; j++) {
            float sj = sc[j];
            rank += (sj > si) || (sj == si && j < i);
        }
        kept = (rank < k) ? 1 : 0;
    }
    keep[i] = kept;
    __syncthreads();
    for (int d = 1; d < 512; d <<= 1) {
        int t = (i >= d) ? keep[i - d] : 0;
        __syncthreads();
        keep[i] += t;
        __syncthreads();
    }
    if (i < nper)
        remap[g * nper + i] = kept ? (g * k + keep[i] - 1) : -1;
}

// ---------------- pool copy fused with tanh-gate + BatchNorm + ReLU ----------------
__global__ void k_pool_copy(const float* __restrict__ Hout, const float* __restrict__ s,
                            const int* __restrict__ remap,
                            const float* __restrict__ bg, const float* __restrict__ bb,
                            const float* __restrict__ bm, const float* __restrict__ bv,
                            float* __restrict__ hp, int n_old) {
    int v = (blockIdx.x * blockDim.x + threadIdx.x) >> 5;
    int lane = threadIdx.x & 31;
    if (v >= n_old) return;
    int r = remap[v];
    if (r < 0) return;
    float t = tanhf(s[v]);
    int c0 = lane * 4;
    float4 h  = *(const float4*)(Hout + (size_t)v * HF + c0);
    float4 g4 = *(const float4*)(bg + c0);
    float4 b4 = *(const float4*)(bb + c0);
    float4 m4 = *(const float4*)(bm + c0);
    float4 v4 = *(const float4*)(bv + c0);
    float4 o;
    o.x = fmaxf(g4.x * (h.x * t - m4.x) * rsqrtf(v4.x + BN_EPS) + b4.x, 0.f);
    o.y = fmaxf(g4.y * (h.y * t - m4.y) * rsqrtf(v4.y + BN_EPS) + b4.y, 0.f);
    o.z = fmaxf(g4.z * (h.z * t - m4.z) * rsqrtf(v4.z + BN_EPS) + b4.z, 0.f);
    o.w = fmaxf(g4.w * (h.w * t - m4.w) * rsqrtf(v4.w + BN_EPS) + b4.w, 0.f);
    *(float4*)(hp + (size_t)r * HF + c0) = o;
}

// ---------------- per-graph feature sum (512 threads, 4-way row split) ----------------
__global__ void k_pooled(const float* __restrict__ X, int nper, float* __restrict__ P) {
    __shared__ float red[4][HF];
    int g = blockIdx.x;
    int f = threadIdx.x & 127, q = threadIdx.x >> 7;
    const float* base = X + (size_t)g * nper * HF + f;
    float acc = 0.f;
    for (int r = q; r < nper; r += 4) acc += base[(size_t)r * HF];
    red[q][f] = acc;
    __syncthreads();
    if (q == 0)
        P[g * HF + f] = red[0][f] + red[1][f] + red[2][f] + red[3][f];
}

// ---------------- readout ----------------
__global__ void k_final(const float* __restrict__ P0, const float* __restrict__ P1,
                        const float* __restrict__ P2,
                        const float* __restrict__ W0, const float* __restrict__ b0,
                        const float* __restrict__ W1, const float* __restrict__ b1,
                        const float* __restrict__ W2, const float* __restrict__ b2,
                        float* __restrict__ out) {
    int idx = blockIdx.x * blockDim.x + threadIdx.x;
    if (idx >= BGR * DOUT) return;
    int b = idx / DOUT, o = idx % DOUT;
    float acc = b0[o] + b1[o] + b2[o];
    const float* p0 = P0 + b * HF;
    const float* p1 = P1 + b * HF;
    const float* p2 = P2 + b * HF;
    const float* w0 = W0 + o * HF;
    const float* w1 = W1 + o * HF;
    const float* w2 = W2 + o * HF;
    #pragma unroll 4
    for (int f = 0; f < HF; f++)
        acc += p0[f] * w0[f] + p1[f] * w1[f] + p2[f] * w2[f];
    out[idx] = acc;
}

// ---------------- host launch ----------------
extern "C" void kernel_launch(void* const* d_in, const int* in_sizes, int n_in,
                              void* d_out, int out_size) {
    const float* x        = (const float*)d_in[0];
    const int*   ei       = (const int*)  d_in[1];
    const float* conv1_W  = (const float*)d_in[2];
    const float* conv1_b  = (const float*)d_in[3];
    const float* conv2_W  = (const float*)d_in[4];
    const float* conv2_b  = (const float*)d_in[5];
    const float* score1_W = (const float*)d_in[6];
    const float* score1_b = (const float*)d_in[7];
    const float* score2_W = (const float*)d_in[8];
    const float* score2_b = (const float*)d_in[9];
    const float* bn1_g    = (const float*)d_in[10];
    const float* bn1_b    = (const float*)d_in[11];
    const float* bn1_m    = (const float*)d_in[12];
    const float* bn1_v    = (const float*)d_in[13];
    const float* bn2_g    = (const float*)d_in[14];
    const float* bn2_b    = (const float*)d_in[15];
    const float* bn2_m    = (const float*)d_in[16];
    const float* bn2_v    = (const float*)d_in[17];
    const float* lin0_W   = (const float*)d_in[18];
    const float* lin0_b   = (const float*)d_in[19];
    const float* lin1_W   = (const float*)d_in[20];
    const float* lin1_b   = (const float*)d_in[21];
    const float* lin2_W   = (const float*)d_in[22];
    const float* lin2_b   = (const float*)d_in[23];
    float* out = (float*)d_out;

    const int* src0 = ei;
    const int* dst0 = ei + EE;

    float *bufA, *bufB, *bufC, *dinv, *hs, *sc, *p0, *p1, *p2;
    int *remap, *rowbase, *rowcnt, *csrsrc;
    u64 *wp1, *wp2;
    cudaGetSymbolAddress((void**)&bufA,   g_bufA);
    cudaGetSymbolAddress((void**)&bufB,   g_bufB);
    cudaGetSymbolAddress((void**)&bufC,   g_bufC);
    cudaGetSymbolAddress((void**)&dinv,   g_dinv);
    cudaGetSymbolAddress((void**)&hs,     g_hs);
    cudaGetSymbolAddress((void**)&sc,     g_sc);
    cudaGetSymbolAddress((void**)&remap,  g_remap);
    cudaGetSymbolAddress((void**)&rowbase,g_rowbase);
    cudaGetSymbolAddress((void**)&rowcnt, g_rowcnt);
    cudaGetSymbolAddress((void**)&csrsrc, g_csrsrc);
    cudaGetSymbolAddress((void**)&wp1,    g_Wp1);
    cudaGetSymbolAddress((void**)&wp2,    g_Wp2);
    cudaGetSymbolAddress((void**)&p0,     g_pool0);
    cudaGetSymbolAddress((void**)&p1,     g_pool1);
    cudaGetSymbolAddress((void**)&p2,     g_pool2);

    // weight packing (cheap, runs every call: deterministic)
    k_packW<<<(64 * HF + 255) / 256, 256>>>(conv1_W, wp1);
    k_packW<<<(64 * HF + 255) / 256, 256>>>(conv2_W, wp2);

    // ---------- layer 0 ----------
    k_csr<<<BGR, 512>>>(src0, dst0, nullptr, NPER0, rowbase, rowcnt, csrsrc, dinv);
    k_gemm2<<<(N0 + 63) / 64, 256>>>(x, wp1, bufB, N0);
    k_agg_hs<<<(N0 + 7) / 8, 256>>>(bufB, csrsrc, rowbase, rowcnt, dinv, conv1_b,
                                    score1_W, bufA, hs, N0);
    k_sagg<<<(N0 + 255) / 256, 256>>>(hs, csrsrc, rowbase, rowcnt, dinv, score1_b, sc, N0);
    k_pool_select<<<BGR, 512>>>(sc, NPER0, K1, remap);
    k_pool_copy<<<(N0 + 7) / 8, 256>>>(bufA, sc, remap, bn1_g, bn1_b, bn1_m, bn1_v, bufC, N0);

    // ---------- layer 1 (remap fused into CSR build) ----------
    k_csr<<<BGR, 512>>>(src0, dst0, remap, K1, rowbase, rowcnt, csrsrc, dinv);
    k_gemm2<<<(N1 + 63) / 64, 256>>>(bufC, wp2, bufB, N1);
    k_agg_hs<<<(N1 + 7) / 8, 256>>>(bufB, csrsrc, rowbase, rowcnt, dinv, conv2_b,
                                    score2_W, bufA, hs, N1);
    k_sagg<<<(N1 + 255) / 256, 256>>>(hs, csrsrc, rowbase, rowcnt, dinv, score2_b, sc, N1);
    k_pool_select<<<BGR, 512>>>(sc, K1, K2, remap);
    k_pool_copy<<<(N1 + 7) / 8, 256>>>(bufA, sc, remap, bn2_g, bn2_b, bn2_m, bn2_v, bufB, N1);

    // ---------- readout ----------
    k_pooled<<<BGR, 512>>>(x,    NPER0, p0);
    k_pooled<<<BGR, 512>>>(bufC, K1,    p1);
    k_pooled<<<BGR, 512>>>(bufB, K2,    p2);
    k_final<<<(BGR * DOUT + 255) / 256, 256>>>(p0, p1, p2,
                                               lin0_W, lin0_b, lin1_W, lin1_b, lin2_W, lin2_b,
                                               out);
}

// round 3
// speedup vs baseline: 1.1398x; 1.0746x over previous
#include <cuda_runtime.h>
#include <math.h>
#include <stdint.h>

// ---------------- problem constants ----------------
#define BGR   128          // graphs
#define NPER0 512          // nodes per graph, layer 0
#define EPG   8192         // edges per graph
#define EE    (BGR*EPG)    // 1048576 total edges
#define N0    (BGR*NPER0)  // 65536
#define K1    410
#define K2    328
#define N1    (BGR*K1)     // 52480  (divisible by 64: 820 tiles)
#define N2    (BGR*K2)     // 41984
#define HF    128          // feature dim (DIN == H == 128)
#define DOUT  10
#define BN_EPS 1e-5f

typedef unsigned long long u64;

// ---------------- static device scratch ----------------
__device__ float g_bufA[(size_t)N0*HF];   // GCN output h
__device__ float g_bufB[(size_t)N0*HF];   // X@W ; later hp2
__device__ float g_bufC[(size_t)N1*HF];   // hp1
__device__ float g_dinv[N0];
__device__ float g_hs[N0];
__device__ int   g_remap[N0];
__device__ int   g_rowbase[N0];
__device__ int   g_rowcnt[N0];
__device__ int   g_csrsrc[EE];
__device__ u64   g_Wp1[64*HF];            // packed (W[2k][c], W[2k+1][c])
__device__ u64   g_Wp2[64*HF];
__device__ float g_pool[3*BGR*HF];        // pooled sums, 3 layers contiguous

// ---------------- packed fp32x2 fma ----------------
__device__ __forceinline__ u64 ffma2(u64 a, u64 b, u64 c) {
    u64 d;
    asm("fma.rn.f32x2 %0, %1, %2, %3;" : "=l"(d) : "l"(a), "l"(b), "l"(c));
    return d;
}

// ---------------- pack both weight matrices in one launch ----------------
__global__ void k_packW2(const float* __restrict__ W1, const float* __restrict__ W2,
                         u64* __restrict__ Wp1, u64* __restrict__ Wp2) {
    int i = blockIdx.x * blockDim.x + threadIdx.x;
    const int n = 64 * HF;
    if (i >= 2 * n) return;
    const float* W = (i < n) ? W1 : W2;
    u64* Wp = (i < n) ? Wp1 : Wp2;
    int j = (i < n) ? i : i - n;
    int kp = j >> 7, c = j & 127;
    u64 lo = __float_as_uint(W[(2 * kp) * HF + c]);
    u64 hi = __float_as_uint(W[(2 * kp + 1) * HF + c]);
    Wp[j] = lo | (hi << 32);
}

// ---------------- CSR build per graph (+ optional remap fusion) ----------------
__global__ void k_csr(const int* __restrict__ src, const int* __restrict__ dst,
                      const int* __restrict__ remap, int nper,
                      int* __restrict__ row_base, int* __restrict__ row_cnt,
                      int* __restrict__ csr_src, float* __restrict__ dinv) {
    __shared__ int cnt[512];
    __shared__ int off[512];
    __shared__ int cur[512];
    int g = blockIdx.x, i = threadIdx.x;
    cnt[i] = 0; cur[i] = 0;
    __syncthreads();
    int ebase = g * EPG;
    for (int t = i; t < EPG; t += 512) {
        int s = src[ebase + t];
        int d = dst[ebase + t];
        if (remap) {
            s = remap[s];
            d = (s >= 0) ? remap[d] : -1;
            if (d < 0) continue;
        }
        atomicAdd(&cnt[d - g * nper], 1);
    }
    __syncthreads();
    int c = cnt[i];
    off[i] = c;
    __syncthreads();
    for (int d = 1; d < 512; d <<= 1) {          // Hillis-Steele inclusive scan
        int t = (i >= d) ? off[i - d] : 0;
        __syncthreads();
        off[i] += t;
        __syncthreads();
    }
    int excl = off[i] - c;
    if (i < nper) {
        row_cnt[g * nper + i]  = c;
        row_base[g * nper + i] = ebase + excl;
        dinv[g * nper + i]     = rsqrtf(1.0f + (float)c);  // +1 self loop
    }
    __syncthreads();
    off[i] = excl;
    __syncthreads();
    for (int t = i; t < EPG; t += 512) {
        int s = src[ebase + t];
        int d = dst[ebase + t];
        if (remap) {
            s = remap[s];
            d = (s >= 0) ? remap[d] : -1;
            if (d < 0) continue;
        }
        int dl = d - g * nper;
        int p = atomicAdd(&cur[dl], 1);
        csr_src[ebase + off[dl] + p] = s;
    }
}

// ---------------- GEMM v3: Y[nrows,128] = X @ W, packed f32x2 ----------------
// 256 threads, 64-row tile, thread: 8 rows x 4 cols. nrows must be /64.
// X fragments via LDS.128 broadcast; 2 CTAs/SM via launch_bounds.
__global__ void __launch_bounds__(256, 2)
k_gemm3(const float* __restrict__ X, const u64* __restrict__ Wp,
        float* __restrict__ Y) {
    __shared__ float Xs[64][HF];                 // 32 KB
    int row0 = blockIdx.x * 64;
    int tid = threadIdx.x;
    #pragma unroll
    for (int j = 0; j < 8; j++) {
        int idx = j * 256 + tid;
        int r = idx >> 5, c4 = idx & 31;
        float4 v = *(const float4*)(X + (size_t)(row0 + r) * HF + c4 * 4);
        *(float4*)(&Xs[r][c4 * 4]) = v;
    }
    __syncthreads();
    int wid = tid >> 5, lane = tid & 31;
    int r0 = wid * 8, c0 = lane * 4;
    u64 acc[8][4] = {};
    const u64* wp = Wp + c0;
    #pragma unroll 1
    for (int kp4 = 0; kp4 < 16; kp4++) {
        const u64* wb = wp + (size_t)(kp4 * 4) * HF;
        ulonglong2 wA0 = *(const ulonglong2*)(wb);
        ulonglong2 wB0 = *(const ulonglong2*)(wb + 2);
        ulonglong2 wA1 = *(const ulonglong2*)(wb + HF);
        ulonglong2 wB1 = *(const ulonglong2*)(wb + HF + 2);
        ulonglong2 wA2 = *(const ulonglong2*)(wb + 2 * HF);
        ulonglong2 wB2 = *(const ulonglong2*)(wb + 2 * HF + 2);
        ulonglong2 wA3 = *(const ulonglong2*)(wb + 3 * HF);
        ulonglong2 wB3 = *(const ulonglong2*)(wb + 3 * HF + 2);
        #pragma unroll
        for (int i = 0; i < 8; i++) {
            ulonglong2 xa = *(const ulonglong2*)(&Xs[r0 + i][kp4 * 8]);      // kp j=0,1
            ulonglong2 xb = *(const ulonglong2*)(&Xs[r0 + i][kp4 * 8 + 4]);  // kp j=2,3
            acc[i][0] = ffma2(xa.x, wA0.x, acc[i][0]);
            acc[i][1] = ffma2(xa.x, wA0.y, acc[i][1]);
            acc[i][2] = ffma2(xa.x, wB0.x, acc[i][2]);
            acc[i][3] = ffma2(xa.x, wB0.y, acc[i][3]);
            acc[i][0] = ffma2(xa.y, wA1.x, acc[i][0]);
            acc[i][1] = ffma2(xa.y, wA1.y, acc[i][1]);
            acc[i][2] = ffma2(xa.y, wB1.x, acc[i][2]);
            acc[i][3] = ffma2(xa.y, wB1.y, acc[i][3]);
            acc[i][0] = ffma2(xb.x, wA2.x, acc[i][0]);
            acc[i][1] = ffma2(xb.x, wA2.y, acc[i][1]);
            acc[i][2] = ffma2(xb.x, wB2.x, acc[i][2]);
            acc[i][3] = ffma2(xb.x, wB2.y, acc[i][3]);
            acc[i][0] = ffma2(xb.y, wA3.x, acc[i][0]);
            acc[i][1] = ffma2(xb.y, wA3.y, acc[i][1]);
            acc[i][2] = ffma2(xb.y, wB3.x, acc[i][2]);
            acc[i][3] = ffma2(xb.y, wB3.y, acc[i][3]);
        }
    }
    #pragma unroll
    for (int i = 0; i < 8; i++) {
        int r = row0 + r0 + i;
        float2 p0 = *(float2*)&acc[i][0];
        float2 p1 = *(float2*)&acc[i][1];
        float2 p2 = *(float2*)&acc[i][2];
        float2 p3 = *(float2*)&acc[i][3];
        float4 o = make_float4(p0.x + p0.y, p1.x + p1.y, p2.x + p2.y, p3.x + p3.y);
        *(float4*)(Y + (size_t)r * HF + c0) = o;
    }
}

// ---------------- GCN aggregation fused with score matvec (warp per dst node) ----
__global__ void k_agg_hs(const float* __restrict__ H,
                         const int* __restrict__ csr_src,
                         const int* __restrict__ row_base, const int* __restrict__ row_cnt,
                         const float* __restrict__ dinv, const float* __restrict__ bias,
                         const float* __restrict__ sW,
                         float* __restrict__ out, float* __restrict__ hs, int n) {
    int w = (blockIdx.x * blockDim.x + threadIdx.x) >> 5;
    int lane = threadIdx.x & 31;
    if (w >= n) return;
    float di = dinv[w];
    int base = row_base[w], cnt = row_cnt[w];
    float ax = 0.f, ay = 0.f, az = 0.f, aw = 0.f;
    int c0 = lane * 4;
    int e = 0;
    for (; e + 2 <= cnt; e += 2) {               // 2-way unroll for MLP
        int s0 = __ldg(&csr_src[base + e]);
        int s1 = __ldg(&csr_src[base + e + 1]);
        float d0 = __ldg(&dinv[s0]);
        float d1 = __ldg(&dinv[s1]);
        float4 h0 = *(const float4*)(H + (size_t)s0 * HF + c0);
        float4 h1 = *(const float4*)(H + (size_t)s1 * HF + c0);
        ax += d0 * h0.x + d1 * h1.x;
        ay += d0 * h0.y + d1 * h1.y;
        az += d0 * h0.z + d1 * h1.z;
        aw += d0 * h0.w + d1 * h1.w;
    }
    if (e < cnt) {
        int s0 = __ldg(&csr_src[base + e]);
        float d0 = __ldg(&dinv[s0]);
        float4 h0 = *(const float4*)(H + (size_t)s0 * HF + c0);
        ax += d0 * h0.x; ay += d0 * h0.y; az += d0 * h0.z; aw += d0 * h0.w;
    }
    float sd = di * di;
    float4 self = *(const float4*)(H + (size_t)w * HF + c0);
    float4 b4 = *(const float4*)(bias + c0);
    float4 o;
    o.x = ax * di + self.x * sd + b4.x;
    o.y = ay * di + self.y * sd + b4.y;
    o.z = az * di + self.z * sd + b4.z;
    o.w = aw * di + self.w * sd + b4.w;
    *(float4*)(out + (size_t)w * HF + c0) = o;
    // fused score matvec
    float4 wv = *(const float4*)(sW + c0);
    float d = o.x * wv.x + o.y * wv.y + o.z * wv.z + o.w * wv.w;
    #pragma unroll
    for (int off = 16; off > 0; off >>= 1) d += __shfl_down_sync(0xFFFFFFFFu, d, off);
    if (lane == 0) hs[w] = d;
}

// ---------------- fused per-graph tail: score-agg + top-k + tanh/BN/ReLU copy ----
// One CTA (512 threads) per graph.
__global__ void k_pool_fused(const float* __restrict__ hs, const float* __restrict__ dinv,
                             const int* __restrict__ csr_src,
                             const int* __restrict__ row_base, const int* __restrict__ row_cnt,
                             const float* __restrict__ Hout, const float* __restrict__ sb,
                             const float* __restrict__ bg, const float* __restrict__ bb,
                             const float* __restrict__ bm, const float* __restrict__ bv,
                             int nper, int k,
                             int* __restrict__ remap, float* __restrict__ hp) {
    __shared__ float hs_s[512];
    __shared__ float di_s[512];
    __shared__ float sc_s[512];
    __shared__ float tn_s[512];      // tanh(score) of kept nodes, by new local id
    __shared__ int   keep[512];
    __shared__ int   inv_s[512];     // new local id -> old local id
    __shared__ float bnp[4][HF];
    int g = blockIdx.x, i = threadIdx.x;

    if (i < nper) {
        hs_s[i] = hs[g * nper + i];
        di_s[i] = dinv[g * nper + i];
    } else { hs_s[i] = 0.f; di_s[i] = 0.f; }
    if (i < HF) {
        bnp[0][i] = bg[i]; bnp[1][i] = bb[i]; bnp[2][i] = bm[i]; bnp[3][i] = bv[i];
    }
    __syncthreads();

    // score aggregation (reads hs/dinv from smem)
    float scv = -1e30f;
    if (i < nper) {
        int base = row_base[g * nper + i], cnt = row_cnt[g * nper + i];
        float acc = 0.f;
        int e = 0;
        for (; e + 2 <= cnt; e += 2) {
            int s0 = __ldg(&csr_src[base + e]) - g * nper;
            int s1 = __ldg(&csr_src[base + e + 1]) - g * nper;
            acc += hs_s[s0] * di_s[s0] + hs_s[s1] * di_s[s1];
        }
        if (e < cnt) {
            int s0 = __ldg(&csr_src[base + e]) - g * nper;
            acc += hs_s[s0] * di_s[s0];
        }
        float di = di_s[i];
        scv = acc * di + hs_s[i] * di * di + sb[0];
    }
    sc_s[i] = scv;
    __syncthreads();

    // exact rank (ties -> lower index wins)
    int kept = 0;
    if (i < nper) {
        float si = scv;
        int rank = 0;
        for (int j = 0; j < nper; j++) {
            float sj = sc_s[j];
            rank += (sj > si) || (sj == si && j < i);
        }
        kept = (rank < k) ? 1 : 0;
    }
    keep[i] = kept;
    __syncthreads();
    for (int d = 1; d < 512; d <<= 1) {          // inclusive scan
        int t = (i >= d) ? keep[i - d] : 0;
        __syncthreads();
        keep[i] += t;
        __syncthreads();
    }
    if (i < nper) {
        int pos = keep[i] - 1;
        remap[g * nper + i] = kept ? (g * k + pos) : -1;
        if (kept) {
            inv_s[pos] = i;
            tn_s[pos]  = tanhf(sc_s[i]);
        }
    }
    __syncthreads();

    // copy + tanh gate + BN + ReLU for the k kept rows (coalesced float4)
    const float* hbase = Hout + (size_t)g * nper * HF;
    float* obase = hp + (size_t)g * k * HF;
    for (int idx = i; idx < k * 32; idx += 512) {
        int rn = idx >> 5, c4 = (idx & 31) * 4;
        int ro = inv_s[rn];
        float t = tn_s[rn];
        float4 h = *(const float4*)(hbase + (size_t)ro * HF + c4);
        float4 o;
        o.x = fmaxf(bnp[0][c4+0] * (h.x * t - bnp[2][c4+0]) * rsqrtf(bnp[3][c4+0] + BN_EPS) + bnp[1][c4+0], 0.f);
        o.y = fmaxf(bnp[0][c4+1] * (h.y * t - bnp[2][c4+1]) * rsqrtf(bnp[3][c4+1] + BN_EPS) + bnp[1][c4+1], 0.f);
        o.z = fmaxf(bnp[0][c4+2] * (h.z * t - bnp[2][c4+2]) * rsqrtf(bnp[3][c4+2] + BN_EPS) + bnp[1][c4+2], 0.f);
        o.w = fmaxf(bnp[0][c4+3] * (h.w * t - bnp[2][c4+3]) * rsqrtf(bnp[3][c4+3] + BN_EPS) + bnp[1][c4+3], 0.f);
        *(float4*)(obase + (size_t)rn * HF + c4) = o;
    }
}

// ---------------- per-graph feature sums, 3 tensors in one launch ----------------
__global__ void k_pooled3(const float* __restrict__ X0, const float* __restrict__ X1,
                          const float* __restrict__ X2, float* __restrict__ P) {
    __shared__ float red[4][HF];
    int g = blockIdx.x, which = blockIdx.y;
    const float* X = (which == 0) ? X0 : ((which == 1) ? X1 : X2);
    int nper = (which == 0) ? NPER0 : ((which == 1) ? K1 : K2);
    int f = threadIdx.x & 127, q = threadIdx.x >> 7;
    const float* base = X + (size_t)g * nper * HF + f;
    float acc = 0.f;
    for (int r = q; r < nper; r += 4) acc += base[(size_t)r * HF];
    red[q][f] = acc;
    __syncthreads();
    if (q == 0)
        P[(which * BGR + g) * HF + f] = red[0][f] + red[1][f] + red[2][f];
    // note: red[3] folded below
    __syncthreads();
    if (q == 0)
        P[(which * BGR + g) * HF + f] += red[3][f];
}

// ---------------- readout ----------------
__global__ void k_final(const float* __restrict__ P,
                        const float* __restrict__ W0, const float* __restrict__ b0,
                        const float* __restrict__ W1, const float* __restrict__ b1,
                        const float* __restrict__ W2, const float* __restrict__ b2,
                        float* __restrict__ out) {
    int idx = blockIdx.x * blockDim.x + threadIdx.x;
    if (idx >= BGR * DOUT) return;
    int b = idx / DOUT, o = idx % DOUT;
    float acc = b0[o] + b1[o] + b2[o];
    const float* p0 = P + b * HF;
    const float* p1 = P + (BGR + b) * HF;
    const float* p2 = P + (2 * BGR + b) * HF;
    const float* w0 = W0 + o * HF;
    const float* w1 = W1 + o * HF;
    const float* w2 = W2 + o * HF;
    #pragma unroll 4
    for (int f = 0; f < HF; f++)
        acc += p0[f] * w0[f] + p1[f] * w1[f] + p2[f] * w2[f];
    out[idx] = acc;
}

// ---------------- host launch ----------------
extern "C" void kernel_launch(void* const* d_in, const int* in_sizes, int n_in,
                              void* d_out, int out_size) {
    const float* x        = (const float*)d_in[0];
    const int*   ei       = (const int*)  d_in[1];
    const float* conv1_W  = (const float*)d_in[2];
    const float* conv1_b  = (const float*)d_in[3];
    const float* conv2_W  = (const float*)d_in[4];
    const float* conv2_b  = (const float*)d_in[5];
    const float* score1_W = (const float*)d_in[6];
    const float* score1_b = (const float*)d_in[7];
    const float* score2_W = (const float*)d_in[8];
    const float* score2_b = (const float*)d_in[9];
    const float* bn1_g    = (const float*)d_in[10];
    const float* bn1_b    = (const float*)d_in[11];
    const float* bn1_m    = (const float*)d_in[12];
    const float* bn1_v    = (const float*)d_in[13];
    const float* bn2_g    = (const float*)d_in[14];
    const float* bn2_b    = (const float*)d_in[15];
    const float* bn2_m    = (const float*)d_in[16];
    const float* bn2_v    = (const float*)d_in[17];
    const float* lin0_W   = (const float*)d_in[18];
    const float* lin0_b   = (const float*)d_in[19];
    const float* lin1_W   = (const float*)d_in[20];
    const float* lin1_b   = (const float*)d_in[21];
    const float* lin2_W   = (const float*)d_in[22];
    const float* lin2_b   = (const float*)d_in[23];
    float* out = (float*)d_out;

    const int* src0 = ei;
    const int* dst0 = ei + EE;

    float *bufA, *bufB, *bufC, *dinv, *hs, *pool;
    int *remap, *rowbase, *rowcnt, *csrsrc;
    u64 *wp1, *wp2;
    cudaGetSymbolAddress((void**)&bufA,   g_bufA);
    cudaGetSymbolAddress((void**)&bufB,   g_bufB);
    cudaGetSymbolAddress((void**)&bufC,   g_bufC);
    cudaGetSymbolAddress((void**)&dinv,   g_dinv);
    cudaGetSymbolAddress((void**)&hs,     g_hs);
    cudaGetSymbolAddress((void**)&remap,  g_remap);
    cudaGetSymbolAddress((void**)&rowbase,g_rowbase);
    cudaGetSymbolAddress((void**)&rowcnt, g_rowcnt);
    cudaGetSymbolAddress((void**)&csrsrc, g_csrsrc);
    cudaGetSymbolAddress((void**)&wp1,    g_Wp1);
    cudaGetSymbolAddress((void**)&wp2,    g_Wp2);
    cudaGetSymbolAddress((void**)&pool,   g_pool);

    k_packW2<<<(2 * 64 * HF + 255) / 256, 256>>>(conv1_W, conv2_W, wp1, wp2);

    // ---------- layer 0 ----------
    k_csr<<<BGR, 512>>>(src0, dst0, nullptr, NPER0, rowbase, rowcnt, csrsrc, dinv);
    k_gemm3<<<N0 / 64, 256>>>(x, wp1, bufB);
    k_agg_hs<<<(N0 + 7) / 8, 256>>>(bufB, csrsrc, rowbase, rowcnt, dinv, conv1_b,
                                    score1_W, bufA, hs, N0);
    k_pool_fused<<<BGR, 512>>>(hs, dinv, csrsrc, rowbase, rowcnt, bufA, score1_b,
                               bn1_g, bn1_b, bn1_m, bn1_v, NPER0, K1, remap, bufC);

    // ---------- layer 1 (remap fused into CSR build) ----------
    k_csr<<<BGR, 512>>>(src0, dst0, remap, K1, rowbase, rowcnt, csrsrc, dinv);
    k_gemm3<<<N1 / 64, 256>>>(bufC, wp2, bufB);
    k_agg_hs<<<(N1 + 7) / 8, 256>>>(bufB, csrsrc, rowbase, rowcnt, dinv, conv2_b,
                                    score2_W, bufA, hs, N1);
    k_pool_fused<<<BGR, 512>>>(hs, dinv, csrsrc, rowbase, rowcnt, bufA, score2_b,
                               bn2_g, bn2_b, bn2_m, bn2_v, K1, K2, remap, bufB);

    // ---------- readout ----------
    dim3 pgrid(BGR, 3);
    k_pooled3<<<pgrid, 512>>>(x, bufC, bufB, pool);
    k_final<<<(BGR * DOUT + 255) / 256, 256>>>(pool,
                                               lin0_W, lin0_b, lin1_W, lin1_b, lin2_W, lin2_b,
                                               out);
}